// round 8
// baseline (speedup 1.0000x reference)
#include <cuda_runtime.h>
#include <math.h>

#define D 32
#define H 128
#define NB 128
#define NSTEPS 8
#define DTf 0.125f
#define LOG2PI 1.837877066409345483560659472811f

// E[m*H+k] = W2[m,k] * (W1 @ W3)[k,m]   (input-independent)
__device__ float g_E[H * H];

static __device__ constexpr float Aa[6][5] = {
    {0.f, 0.f, 0.f, 0.f, 0.f},
    {0.2f, 0.f, 0.f, 0.f, 0.f},
    {3.f/40.f, 9.f/40.f, 0.f, 0.f, 0.f},
    {44.f/45.f, -56.f/15.f, 32.f/9.f, 0.f, 0.f},
    {19372.f/6561.f, -25360.f/2187.f, 64448.f/6561.f, -212.f/729.f, 0.f},
    {9017.f/3168.f, -355.f/33.f, 46732.f/5247.f, 49.f/176.f, -5103.f/18656.f}
};
static __device__ constexpr float Bb[6] = {
    35.f/384.f, 0.f, 500.f/1113.f, 125.f/192.f, -2187.f/6784.f, 11.f/84.f
};
static __device__ constexpr float Cc[6] = {0.f, 0.2f, 0.3f, 0.8f, 8.f/9.f, 1.f};

__global__ void precompute_E_kernel(const float* __restrict__ W1,
                                    const float* __restrict__ W2,
                                    const float* __restrict__ W3) {
    __shared__ float sW1[H * D];
    __shared__ float sw3col[D];
    int m = blockIdx.x;
    int k = threadIdx.x;
    for (int idx = k; idx < H * D; idx += H) sW1[idx] = W1[idx];
    if (k < D) sw3col[k] = W3[k * H + m];
    __syncthreads();
    float acc = 0.f;
#pragma unroll
    for (int j = 0; j < D; j++) acc += sW1[k * D + j] * sw3col[j];
    g_E[m * H + k] = W2[m * H + k] * acc;
}

__device__ __forceinline__ float ftanh(float z) {
    float e = __expf(2.f * z);
    return 1.f - __fdividef(2.f, e + 1.f);
}

__global__ __launch_bounds__(512, 1)
void ode_kernel(const float* __restrict__ x0,
                const float* __restrict__ W1g,
                const float* __restrict__ u1g,
                const float* __restrict__ b1g,
                const float* __restrict__ W2g,
                const float* __restrict__ b2g,
                const float* __restrict__ W3g,
                const float* __restrict__ b3g,
                const float* __restrict__ precg,
                float* __restrict__ out)
{
    __shared__ __align__(16) float sx[D];
    __shared__ __align__(16) float sy[D];
    __shared__ __align__(16) float sh1[H];
    __shared__ __align__(16) float sd1[H];
    __shared__ __align__(16) float sh2[H];
    __shared__ __align__(16) float skv[6 * D];
    __shared__ float sred[52];

    const int tid  = threadIdx.x;
    const int lane = tid & 31;
    const int wid  = tid >> 5;
    const int b    = blockIdx.x;

    const int r  = tid >> 2;     // hidden row (4 threads/row)
    const int q  = tid & 3;      // quarter of K
    const int ro = tid >> 4;     // output row (16 threads/row)
    const int so = tid & 15;

    // ---- register-resident weights (quarter rows) ----
    float4 W1q[2], W2q[8], Eq[8], W3c[2];
    {
        const float4* p1 = (const float4*)(W1g + r * D + q * 8);
        W1q[0] = p1[0]; W1q[1] = p1[1];
        const float4* p2 = (const float4*)(W2g + r * H + q * 32);
        const float4* pe = (const float4*)(g_E + r * H + q * 32);
#pragma unroll
        for (int i = 0; i < 8; i++) { W2q[i] = p2[i]; Eq[i] = pe[i]; }
        const float4* p3 = (const float4*)(W3g + ro * H + so * 8);
        W3c[0] = p3[0]; W3c[1] = p3[1];
    }
    const float u1r = u1g[r];
    const float b1r = b1g[r];
    const float b2r = b2g[r];
    const float b3r = b3g[ro];
    const float prr = precg[ro];

    // deferred-reduction accumulators
    float accld = 0.f;   // sum_s Bb[s] * trrow            (x4 redundancy)
    float acckl = 0.f;   // sum_s Bb[s] * omt * trrow      (x4 redundancy)
    float kacc  = 0.f;   // owner-only dkl dot terms

    if (tid < D) { float v = x0[b * D + tid]; sx[tid] = v; sy[tid] = v; }
    __syncthreads();

#pragma unroll 1
    for (int step = 0; step < NSTEPS; step++) {
        const float t0 = (float)step * DTf;
#pragma unroll
        for (int s = 0; s < 6; s++) {
            const float t   = t0 + Cc[s] * DTf;
            const float omt = 1.f - t;
            const float bct = Bb[s];
            const float bco = Bb[s] * omt;

            // ---- phase A: h1 = tanh(W1 x + t u1 + b1), 4 thr/row ----
            {
                const float4* xv = ((const float4*)sx) + q * 2;
                float4 xa = xv[0], xb = xv[1];
                float a0 = W1q[0].x * xa.x, a1 = W1q[0].y * xa.y;
                float a2 = W1q[0].z * xa.z, a3 = W1q[0].w * xa.w;
                a0 = fmaf(W1q[1].x, xb.x, a0); a1 = fmaf(W1q[1].y, xb.y, a1);
                a2 = fmaf(W1q[1].z, xb.z, a2); a3 = fmaf(W1q[1].w, xb.w, a3);
                float p = (a0 + a1) + (a2 + a3);
                p += __shfl_xor_sync(0xffffffffu, p, 1);
                p += __shfl_xor_sync(0xffffffffu, p, 2);
                float h = ftanh(p + t * u1r + b1r);
                if (q == 0) {
                    sh1[r] = h;
                    sd1[r] = fmaf(-h, h, 1.f);
                }
            }
            __syncthreads();

            // ---- phase B: h2 = tanh(W2 h1 + b2) fused with E d1 (trace row) ----
            {
                const float4* hv = ((const float4*)sh1) + q * 8;
                const float4* dv = ((const float4*)sd1) + q * 8;
                float a0 = 0.f, a1 = 0.f, a2 = 0.f, a3 = 0.f;
                float g0 = 0.f, g1 = 0.f, g2 = 0.f, g3 = 0.f;
#pragma unroll
                for (int c = 0; c < 8; c++) {
                    float4 h4 = hv[c], w = W2q[c];
                    a0 = fmaf(w.x, h4.x, a0); a1 = fmaf(w.y, h4.y, a1);
                    a2 = fmaf(w.z, h4.z, a2); a3 = fmaf(w.w, h4.w, a3);
                    float4 d4 = dv[c], e = Eq[c];
                    g0 = fmaf(e.x, d4.x, g0); g1 = fmaf(e.y, d4.y, g1);
                    g2 = fmaf(e.z, d4.z, g2); g3 = fmaf(e.w, d4.w, g3);
                }
                float pz = (a0 + a1) + (a2 + a3);
                float gs = (g0 + g1) + (g2 + g3);
                pz += __shfl_xor_sync(0xffffffffu, pz, 1);
                gs += __shfl_xor_sync(0xffffffffu, gs, 1);
                pz += __shfl_xor_sync(0xffffffffu, pz, 2);
                gs += __shfl_xor_sync(0xffffffffu, gs, 2);
                float h2 = ftanh(pz + b2r);
                float trrow = fmaf(-h2, h2, 1.f) * gs;
                accld = fmaf(bct, trrow, accld);
                acckl = fmaf(bco, trrow, acckl);
                if (q == 0) sh2[r] = h2;
            }
            __syncthreads();

            // ---- phase C: k = W3 h2 + b3, 16 thr/row; owner bookkeeping ----
            {
                float xs = sx[ro];   // prefetch (hidden under FMAs)
                float yv = sy[ro];
                const float4* h3 = ((const float4*)sh2) + so * 2;
                float4 ha = h3[0], hb = h3[1];
                float c0 = W3c[0].x * ha.x, c1 = W3c[0].y * ha.y;
                float c2 = W3c[0].z * ha.z, c3 = W3c[0].w * ha.w;
                c0 = fmaf(W3c[1].x, hb.x, c0); c1 = fmaf(W3c[1].y, hb.y, c1);
                c2 = fmaf(W3c[1].z, hb.z, c2); c3 = fmaf(W3c[1].w, hb.w, c3);
                float o = (c0 + c1) + (c2 + c3);
                o += __shfl_xor_sync(0xffffffffu, o, 1);
                o += __shfl_xor_sync(0xffffffffu, o, 2);
                o += __shfl_xor_sync(0xffffffffu, o, 4);
                o += __shfl_xor_sync(0xffffffffu, o, 8);
                o += b3r;
                if (so == 0) {
                    float lp = fmaf(-0.5f * xs, xs, -0.5f * LOG2PI);
                    float gl = -prr * xs;
                    float ca = bct * (-0.5f) * omt * omt;
                    float cb = bct * (-0.5f) * omt * (1.f + t);
                    kacc = fmaf(o, fmaf(ca, lp, cb * gl), kacc);
                    skv[s * D + ro] = o;
                    float xn;
                    if (s < 5) {
                        float acc = Aa[s + 1][s] * o;
#pragma unroll
                        for (int l = 0; l < s; l++)
                            acc = fmaf(Aa[s + 1][l], skv[l * D + ro], acc);
                        xn = fmaf(DTf, acc, yv);
                    } else {
                        float acc = Bb[0] * skv[0 * D + ro] + Bb[2] * skv[2 * D + ro]
                                  + Bb[3] * skv[3 * D + ro] + Bb[4] * skv[4 * D + ro]
                                  + Bb[5] * o;
                        xn = fmaf(DTf, acc, yv);
                        sy[ro] = xn;
                    }
                    sx[ro] = xn;
                }
            }
            __syncthreads();
        }
    }

    // ---- z output ----
    if (so == 0) out[b * D + ro] = sy[ro];

    // ---- single block reduction of all deferred accumulators ----
#pragma unroll
    for (int o = 16; o; o >>= 1) {
        accld += __shfl_xor_sync(0xffffffffu, accld, o);
        acckl += __shfl_xor_sync(0xffffffffu, acckl, o);
        kacc  += __shfl_xor_sync(0xffffffffu, kacc,  o);
    }
    if (lane == 0) {
        sred[wid]      = accld;
        sred[16 + wid] = acckl;
        sred[32 + wid] = kacc;
    }
    if (wid == 2) {
        float xv0 = x0[b * D + lane];
        float lp = fmaf(-0.5f * xv0, xv0, -0.5f * LOG2PI);
#pragma unroll
        for (int o = 16; o; o >>= 1)
            lp += __shfl_xor_sync(0xffffffffu, lp, o);
        if (lane == 0) sred[48] = lp;
    }
    __syncthreads();

    if (wid == 0) {
        float v1 = (lane < 16) ? sred[lane]      : 0.f;
        float v2 = (lane < 16) ? sred[16 + lane] : 0.f;
        float v3 = (lane < 16) ? sred[32 + lane] : 0.f;
#pragma unroll
        for (int o = 8; o; o >>= 1) {
            v1 += __shfl_xor_sync(0xffffffffu, v1, o);
            v2 += __shfl_xor_sync(0xffffffffu, v2, o);
            v3 += __shfl_xor_sync(0xffffffffu, v3, o);
        }
        if (lane == 0) {
            // accld/acckl counted 4x (4 threads per hidden row)
            float log_det = -DTf * 0.25f * v1;
            float kl      =  DTf * v3 - DTf * 0.25f * v2;
            out[NB * D + b]      = sred[48] + log_det;
            out[NB * D + NB + b] = kl;
        }
    }
}

extern "C" void kernel_launch(void* const* d_in, const int* in_sizes, int n_in,
                              void* d_out, int out_size) {
    const float* x0   = (const float*)d_in[0];
    const float* W1   = (const float*)d_in[1];
    const float* u1   = (const float*)d_in[2];
    const float* b1   = (const float*)d_in[3];
    const float* W2   = (const float*)d_in[4];
    const float* b2   = (const float*)d_in[5];
    const float* W3   = (const float*)d_in[6];
    const float* b3   = (const float*)d_in[7];
    const float* prec = (const float*)d_in[8];
    float* out = (float*)d_out;

    precompute_E_kernel<<<H, H>>>(W1, W2, W3);
    ode_kernel<<<NB, 512>>>(x0, W1, u1, b1, W2, b2, W3, b3, prec, out);
}

// round 9
// speedup vs baseline: 1.4940x; 1.4940x over previous
#include <cuda_runtime.h>
#include <math.h>

#define D 32
#define H 128
#define NB 128
#define NSTEPS 8
#define DTf 0.125f
#define LOG2PI 1.837877066409345483560659472811f

// E[m*H+k] = W2[m,k] * (W1 @ W3)[k,m]   (input-independent)
__device__ float g_E[H * H];

static __device__ constexpr float Aa[6][5] = {
    {0.f, 0.f, 0.f, 0.f, 0.f},
    {0.2f, 0.f, 0.f, 0.f, 0.f},
    {3.f/40.f, 9.f/40.f, 0.f, 0.f, 0.f},
    {44.f/45.f, -56.f/15.f, 32.f/9.f, 0.f, 0.f},
    {19372.f/6561.f, -25360.f/2187.f, 64448.f/6561.f, -212.f/729.f, 0.f},
    {9017.f/3168.f, -355.f/33.f, 46732.f/5247.f, 49.f/176.f, -5103.f/18656.f}
};
static __device__ constexpr float Bb[6] = {
    35.f/384.f, 0.f, 500.f/1113.f, 125.f/192.f, -2187.f/6784.f, 11.f/84.f
};
static __device__ constexpr float Cc[6] = {0.f, 0.2f, 0.3f, 0.8f, 8.f/9.f, 1.f};

__global__ void precompute_E_kernel(const float* __restrict__ W1,
                                    const float* __restrict__ W2,
                                    const float* __restrict__ W3) {
    __shared__ float sW1[H * D];
    __shared__ float sw3col[D];
    int m = blockIdx.x;
    int k = threadIdx.x;
    for (int idx = k; idx < H * D; idx += H) sW1[idx] = W1[idx];
    if (k < D) sw3col[k] = W3[k * H + m];
    __syncthreads();
    float acc = 0.f;
#pragma unroll
    for (int j = 0; j < D; j++) acc += sW1[k * D + j] * sw3col[j];
    g_E[m * H + k] = W2[m * H + k] * acc;
}

__device__ __forceinline__ float ftanh(float z) {
    float e = __expf(2.f * z);
    return 1.f - __fdividef(2.f, e + 1.f);
}

__global__ __launch_bounds__(256, 1)
void ode_kernel(const float* __restrict__ x0,
                const float* __restrict__ W1g,
                const float* __restrict__ u1g,
                const float* __restrict__ b1g,
                const float* __restrict__ W2g,
                const float* __restrict__ b2g,
                const float* __restrict__ W3g,
                const float* __restrict__ b3g,
                const float* __restrict__ precg,
                float* __restrict__ out)
{
    __shared__ __align__(16) float sx[D];       // current stage state
    __shared__ __align__(16) float sh1[H];
    __shared__ __align__(16) float sh2[H];
    __shared__ __align__(16) float skv[6][D];   // stage k vectors
    __shared__ float sred[32];

    const int tid  = threadIdx.x;
    const int lane = tid & 31;
    const int wid  = tid >> 5;
    const int r2   = tid >> 1;   // hidden row (pair)
    const int half = tid & 1;    // which K-half
    const int r3   = tid >> 3;   // output row (group of 8)
    const int sub  = tid & 7;
    const int b    = blockIdx.x;

    // ---- register-resident weights ----
    float4 W1h[4], W2h[16], Eh[16], W3c[4];
    {
        const float4* p = (const float4*)(W1g + r2 * D + half * 16);
#pragma unroll
        for (int i = 0; i < 4; i++) W1h[i] = p[i];
        const float4* q = (const float4*)(W2g + r2 * H + half * 64);
        const float4* e = (const float4*)(g_E + r2 * H + half * 64);
#pragma unroll
        for (int i = 0; i < 16; i++) { W2h[i] = q[i]; Eh[i] = e[i]; }
        const float4* w3 = (const float4*)(W3g + r3 * H + sub * 16);
#pragma unroll
        for (int i = 0; i < 4; i++) W3c[i] = w3[i];
    }
    const float u1r = u1g[r2];
    const float b1r = b1g[r2];
    const float b2r = b2g[r2];
    const float b3r = b3g[r3];
    const float prr = precg[r3];

    // deferred accumulators (reduced once in epilogue)
    float accld = 0.f;   // sum_s Bb[s] * (trace partial)
    float acckl = 0.f;   // sum_s Bb[s] * (1-t) * (trace partial)
    float kacc  = 0.f;   // owner-only dkl dot terms

    // per-row ODE state in owner registers (sub==0)
    float xreg = x0[b * D + r3];
    float yreg = xreg;

    if (tid < D) sx[tid] = x0[b * D + tid];
    __syncthreads();

#pragma unroll 1
    for (int step = 0; step < NSTEPS; step++) {
        const float t0 = (float)step * DTf;
#pragma unroll
        for (int s = 0; s < 6; s++) {
            const float t   = t0 + Cc[s] * DTf;
            const float omt = 1.f - t;
            const float bct = Bb[s];
            const float bco = Bb[s] * omt;

            // ---- phase A: layer 1, pair-split K ----
            {
                const float4* xv = ((const float4*)sx) + half * 4;
                float a0 = 0.f, a1 = 0.f, a2 = 0.f, a3 = 0.f;
#pragma unroll
                for (int c = 0; c < 4; c++) {
                    float4 w = W1h[c], x4 = xv[c];
                    a0 = fmaf(w.x, x4.x, a0); a1 = fmaf(w.y, x4.y, a1);
                    a2 = fmaf(w.z, x4.z, a2); a3 = fmaf(w.w, x4.w, a3);
                }
                float p = (a0 + a1) + (a2 + a3);
                p += __shfl_xor_sync(0xffffffffu, p, 1);
                float h = ftanh(p + t * u1r + b1r);
                if (!half) sh1[r2] = h;
            }
            __syncthreads();

            // ---- phase B: h2 = tanh(W2 h1 + b2) fused with E d1 (deferred trace) ----
            {
                const float4* hv = ((const float4*)sh1) + half * 16;
                float a0 = 0.f, a1 = 0.f, a2 = 0.f, a3 = 0.f;
                float g0 = 0.f, g1 = 0.f, g2 = 0.f, g3 = 0.f;
#pragma unroll 8
                for (int c = 0; c < 16; c++) {
                    float4 h4 = hv[c];
                    float4 w = W2h[c], e = Eh[c];
                    a0 = fmaf(w.x, h4.x, a0); a1 = fmaf(w.y, h4.y, a1);
                    a2 = fmaf(w.z, h4.z, a2); a3 = fmaf(w.w, h4.w, a3);
                    float d0 = fmaf(-h4.x, h4.x, 1.f);
                    float d1 = fmaf(-h4.y, h4.y, 1.f);
                    float d2 = fmaf(-h4.z, h4.z, 1.f);
                    float d3 = fmaf(-h4.w, h4.w, 1.f);
                    g0 = fmaf(e.x, d0, g0); g1 = fmaf(e.y, d1, g1);
                    g2 = fmaf(e.z, d2, g2); g3 = fmaf(e.w, d3, g3);
                }
                float pz = (a0 + a1) + (a2 + a3);
                pz += __shfl_xor_sync(0xffffffffu, pz, 1);
                float h2 = ftanh(pz + b2r);
                if (!half) sh2[r2] = h2;
                // gs stays as this thread's half-row partial; summing accld over
                // all 256 threads reconstructs the full trace (dup factor 1).
                float gs = (g0 + g1) + (g2 + g3);
                float trp = fmaf(-h2, h2, 1.f) * gs;
                accld = fmaf(bct, trp, accld);
                acckl = fmaf(bco, trp, acckl);
            }
            __syncthreads();

            // ---- phase C: layer 3 (8 threads/row) + owner bookkeeping ----
            {
                const float4* hv = ((const float4*)sh2) + sub * 4;
                float a0 = 0.f, a1 = 0.f, a2 = 0.f, a3 = 0.f;
#pragma unroll
                for (int c = 0; c < 4; c++) {
                    float4 w = W3c[c], h4 = hv[c];
                    a0 = fmaf(w.x, h4.x, a0); a1 = fmaf(w.y, h4.y, a1);
                    a2 = fmaf(w.z, h4.z, a2); a3 = fmaf(w.w, h4.w, a3);
                }
                float o = (a0 + a1) + (a2 + a3);
                o += __shfl_xor_sync(0xffffffffu, o, 1);
                o += __shfl_xor_sync(0xffffffffu, o, 2);
                o += __shfl_xor_sync(0xffffffffu, o, 4);
                if (sub == 0) {
                    o += b3r;
                    skv[s][r3] = o;
                    float xs = xreg;
                    // dkl dot terms folded with stage coefficients
                    float lp = fmaf(-0.5f * xs, xs, -0.5f * LOG2PI);
                    float gl = -prr * xs;
                    float ca = bct * (-0.5f) * omt * omt;
                    float cb = bct * (-0.5f) * omt * (1.f + t);
                    kacc = fmaf(o, fmaf(ca, lp, cb * gl), kacc);
                    float xn;
                    if (s < 5) {
                        float acc = Aa[s + 1][s] * o;
#pragma unroll
                        for (int l = 0; l < s; l++)
                            acc = fmaf(Aa[s + 1][l], skv[l][r3], acc);
                        xn = fmaf(DTf, acc, yreg);
                    } else {
                        float acc = Bb[0] * skv[0][r3] + Bb[2] * skv[2][r3]
                                  + Bb[3] * skv[3][r3] + Bb[4] * skv[4][r3]
                                  + Bb[5] * o;
                        xn = fmaf(DTf, acc, yreg);
                        yreg = xn;
                    }
                    xreg = xn;
                    sx[r3] = xn;
                }
            }
            __syncthreads();
        }
    }

    // ---- z output straight from owner registers ----
    if (sub == 0) out[b * D + r3] = yreg;

    // ---- single light reduction of deferred accumulators ----
#pragma unroll
    for (int o = 16; o; o >>= 1) {
        accld += __shfl_xor_sync(0xffffffffu, accld, o);
        acckl += __shfl_xor_sync(0xffffffffu, acckl, o);
        kacc  += __shfl_xor_sync(0xffffffffu, kacc,  o);
    }
    if (lane == 0) {
        sred[wid]      = accld;
        sred[8 + wid]  = acckl;
        sred[16 + wid] = kacc;
    }
    if (wid == 1) {   // log_px0 term
        float xv = x0[b * D + lane];
        float lp = fmaf(-0.5f * xv, xv, -0.5f * LOG2PI);
#pragma unroll
        for (int o = 16; o; o >>= 1)
            lp += __shfl_xor_sync(0xffffffffu, lp, o);
        if (lane == 0) sred[24] = lp;
    }
    __syncthreads();

    if (wid == 0) {
        float v1 = (lane < 8) ? sred[lane]      : 0.f;
        float v2 = (lane < 8) ? sred[8 + lane]  : 0.f;
        float v3 = (lane < 8) ? sred[16 + lane] : 0.f;
#pragma unroll
        for (int o = 4; o; o >>= 1) {
            v1 += __shfl_xor_sync(0xffffffffu, v1, o);
            v2 += __shfl_xor_sync(0xffffffffu, v2, o);
            v3 += __shfl_xor_sync(0xffffffffu, v3, o);
        }
        if (lane == 0) {
            out[NB * D + b]      = sred[24] - DTf * v1;   // log_px0 + log_det
            out[NB * D + NB + b] = DTf * (v3 - v2);       // kl
        }
    }
}

extern "C" void kernel_launch(void* const* d_in, const int* in_sizes, int n_in,
                              void* d_out, int out_size) {
    const float* x0   = (const float*)d_in[0];
    const float* W1   = (const float*)d_in[1];
    const float* u1   = (const float*)d_in[2];
    const float* b1   = (const float*)d_in[3];
    const float* W2   = (const float*)d_in[4];
    const float* b2   = (const float*)d_in[5];
    const float* W3   = (const float*)d_in[6];
    const float* b3   = (const float*)d_in[7];
    const float* prec = (const float*)d_in[8];
    float* out = (float*)d_out;

    precompute_E_kernel<<<H, H>>>(W1, W2, W3);
    ode_kernel<<<NB, 256>>>(x0, W1, u1, b1, W2, b2, W3, b3, prec, out);
}